// round 9
// baseline (speedup 1.0000x reference)
#include <cuda_runtime.h>
#include <cuda_fp16.h>
#include <math.h>

// Problem constants
#define BTOT   1792          // N*D*H = 1*32*56
#define CH_STR 7168          // 128*56
#define XPLANE 100352        // 32*56*56 == BTOT*56
#define NQKV   100352.0
#define NSIM   5619712.0     // BTOT*56*56
#define EPSBN  1e-5f

// ---------------- scratch (device globals; no runtime alloc) ----------------
__device__ float g_qkv[BTOT * 128 * 56];   // [b][o][i]  o = g*16+cc (q:0-3,k:4-7,v:8-15)
__device__ float g_so [BTOT * 128 * 56];   // [b][o2][i]
__device__ double g_qsum[128], g_qsq[128];
__device__ double g_ssum[24],  g_ssq[24];
__device__ double g_osum[128], g_osq[128];
// precomputed relative-embedding moment tables
__device__ float g_SR[8][56];
__device__ float g_TQ[10][56];
__device__ float g_TK[10][56];

__constant__ int   c_PA[10] = {0,0,0,0,1,1,1,2,2,3};
__constant__ int   c_PB[10] = {0,1,2,3,1,2,3,2,3,3};
__constant__ float c_PW[10] = {1.f,2.f,2.f,2.f,1.f,2.f,2.f,1.f,2.f,1.f};

// ---------------- K_init: zero accumulators + prefix tables -----------------
__global__ void k_init(const float* __restrict__ relative) {
    __shared__ float rel[8][112];
    int t = threadIdx.x;
    if (t < 128) { g_qsum[t] = 0.0; g_qsq[t] = 0.0; g_osum[t] = 0.0; g_osq[t] = 0.0; }
    if (t < 24)  { g_ssum[t] = 0.0; g_ssq[t] = 0.0; }
    for (int idx = t; idx < 8 * 111; idx += 256)
        rel[idx / 111][idx % 111] = relative[idx];
    __syncthreads();
    for (int task = t; task < 448; task += 256) {
        int c = task / 56, i = task % 56;
        float s = 0.f;
        for (int d = 0; d < 56; ++d) s += rel[c][i + d];
        g_SR[c][i] = s;
    }
    for (int task = t; task < 1120; task += 256) {
        int p = task / 56, i = task % 56;
        int pp = p % 10; int isK = (p >= 10) ? 4 : 0;
        int a = c_PA[pp] + isK, bb = c_PB[pp] + isK;
        float s = 0.f;
        for (int d = 0; d < 56; ++d) s += rel[a][i + d] * rel[bb][i + d];
        s *= c_PW[pp];
        if (isK) g_TK[pp][i] = s; else g_TQ[pp][i] = s;
    }
}

// ---------------- K1: qkv = w @ x  (+ per-channel stats) --------------------
__global__ void __launch_bounds__(256) k_qkv(const float* __restrict__ x,
                                             const float* __restrict__ w) {
    __shared__ float xs[64][57];
    __shared__ float ws[128][65];
    const int b = blockIdx.x;
    for (int t = threadIdx.x; t < 64 * 56; t += 256) {
        int c = t / 56, i = t % 56;
        xs[c][i] = x[c * XPLANE + b * 56 + i];
    }
    for (int t = threadIdx.x; t < 128 * 64; t += 256)
        ws[t >> 6][t & 63] = w[t];
    __syncthreads();

    const int og = threadIdx.x >> 3;
    const int ig = threadIdx.x & 7;
    const int o0 = og * 4, i0 = ig * 7;
    float acc[4][7];
#pragma unroll
    for (int a = 0; a < 4; a++)
#pragma unroll
        for (int c2 = 0; c2 < 7; c2++) acc[a][c2] = 0.f;

    for (int c = 0; c < 64; ++c) {
        float w0 = ws[o0][c], w1 = ws[o0 + 1][c], w2 = ws[o0 + 2][c], w3 = ws[o0 + 3][c];
#pragma unroll
        for (int ii = 0; ii < 7; ++ii) {
            float xv = xs[c][i0 + ii];
            acc[0][ii] += w0 * xv; acc[1][ii] += w1 * xv;
            acc[2][ii] += w2 * xv; acc[3][ii] += w3 * xv;
        }
    }
    float* outb = g_qkv + (size_t)b * CH_STR;
#pragma unroll
    for (int oo = 0; oo < 4; ++oo) {
        float s = 0.f, sq = 0.f;
#pragma unroll
        for (int ii = 0; ii < 7; ++ii) {
            float v = acc[oo][ii];
            outb[(o0 + oo) * 56 + i0 + ii] = v;
            s += v; sq += v * v;
        }
        for (int off = 4; off; off >>= 1) {
            s  += __shfl_down_sync(0xffffffffu, s,  off);
            sq += __shfl_down_sync(0xffffffffu, sq, off);
        }
        if (ig == 0) {
            atomicAdd(&g_qsum[o0 + oo], (double)s);
            atomicAdd(&g_qsq [o0 + oo], (double)sq);
        }
    }
}

// ---------------- K2: analytic sim moments (folds qkv-BN finalize) ----------
__global__ void __launch_bounds__(256) k_mom(const float* __restrict__ qg,
                                             const float* __restrict__ qb) {
    __shared__ float sQs[128], sQo[128];
    const int b = blockIdx.x;
    {
        int o = threadIdx.x;
        if (o < 128) {
            double inv = 1.0 / NQKV;
            double m = g_qsum[o] * inv;
            double v = g_qsq[o] * inv - m * m;
            float sc = qg[o] * rsqrtf((float)v + EPSBN);
            sQs[o] = sc;
            sQo[o] = qb[o] - (float)m * sc;
        }
    }
    __syncthreads();

    const int g = threadIdx.x >> 5;
    const int lane = threadIdx.x & 31;
    const float* base = g_qkv + (size_t)b * CH_STR + g * 16 * 56;

    float part[32];
#pragma unroll
    for (int v = 0; v < 32; ++v) part[v] = 0.f;

#pragma unroll
    for (int ii = 0; ii < 2; ++ii) {
        int i = lane + ii * 32;
        if (i < 56) {
            float q[4], k[4];
#pragma unroll
            for (int c = 0; c < 4; ++c) {
                int oq = g * 16 + c, ok = g * 16 + 4 + c;
                q[c] = base[c * 56 + i]       * sQs[oq] + sQo[oq];
                k[c] = base[(4 + c) * 56 + i] * sQs[ok] + sQo[ok];
            }
#pragma unroll
            for (int c = 0; c < 4; ++c) {
                part[c]     += q[c];
                part[4 + c] += k[c];
                part[28] += q[c] * g_SR[c][i];
                part[30] += k[c] * g_SR[4 + c][i];
            }
#pragma unroll
            for (int p = 0; p < 10; ++p) {
                float pq = q[c_PA[p]] * q[c_PB[p]];
                float pk = k[c_PA[p]] * k[c_PB[p]];
                part[8 + p]  += pq;
                part[18 + p] += pk;
                part[29] += pq * g_TQ[p][i];
                part[31] += pk * g_TK[p][i];
            }
        }
    }
#pragma unroll
    for (int v = 0; v < 32; ++v)
        for (int off = 16; off; off >>= 1)
            part[v] += __shfl_down_sync(0xffffffffu, part[v], off);

    if (lane == 0) {
        float S1 = 0.f, S2 = 0.f;
#pragma unroll
        for (int c = 0; c < 4; ++c) S1 += part[c] * part[4 + c];
#pragma unroll
        for (int p = 0; p < 10; ++p) S2 += c_PW[p] * part[8 + p] * part[18 + p];
        atomicAdd(&g_ssum[g],      (double)S1);
        atomicAdd(&g_ssq [g],      (double)S2);
        atomicAdd(&g_ssum[8 + g],  (double)(0.1f  * part[28]));
        atomicAdd(&g_ssq [8 + g],  (double)(0.01f * part[29]));
        atomicAdd(&g_ssum[16 + g], (double)(0.1f  * part[30]));
        atomicAdd(&g_ssq [16 + g], (double)(0.01f * part[31]));
    }
}

// ---- warp reduce-scatter over tj (lane bits 1..3): masks 2,4,8 -------------
// Input: av[16], v = 2*ch + r. Output: rows r=0,1 for channel ch = bitrev3(tj).
__device__ __forceinline__ void reduce_scatter16p(const float* av, int tj,
                                                  float& o0, float& o1) {
    float a8[8];
#pragma unroll
    for (int v = 0; v < 8; ++v) {
        float snd = (tj & 1) ? av[v] : av[8 + v];
        float kp  = (tj & 1) ? av[8 + v] : av[v];
        a8[v] = kp + __shfl_xor_sync(0xffffffffu, snd, 2);
    }
    float a4[4];
#pragma unroll
    for (int v = 0; v < 4; ++v) {
        float snd = (tj & 2) ? a8[v] : a8[4 + v];
        float kp  = (tj & 2) ? a8[4 + v] : a8[v];
        a4[v] = kp + __shfl_xor_sync(0xffffffffu, snd, 4);
    }
    float a2[2];
#pragma unroll
    for (int v = 0; v < 2; ++v) {
        float snd = (tj & 4) ? a4[v] : a4[2 + v];
        float kp  = (tj & 4) ? a4[2 + v] : a4[v];
        a2[v] = kp + __shfl_xor_sync(0xffffffffu, snd, 8);
    }
    o0 = a2[0]; o1 = a2[1];
}

// ---------------- K3: attention — 448 threads, 2 heads/iter, rel dedup ------
// lane: bit0 = h (head parity), bits1-3 = tj, bit4 = ig. ti = warp*2 + ig.
// Adjacent lanes (h=0/1) share (ti,tj) -> identical rel rows -> LDS broadcast.
__global__ void __launch_bounds__(448, 2) k_attn(const float* __restrict__ relative,
                                                 const float* __restrict__ qg,
                                                 const float* __restrict__ qb,
                                                 const float* __restrict__ sg,
                                                 const float* __restrict__ sb) {
    __shared__ __align__(16) float qsT[8][56][4];
    __shared__ __align__(16) float ksT[8][56][4];
    __shared__ __align__(16) float vsT[8][56][8];
    __shared__ __align__(16) __half relQK[111][8];  // {relq[0..3][d], relk[0..3][110-d]}
    __shared__ __align__(16) __half relV[111][8];   // {relv[0..7][d]}
    __shared__ __align__(16) float SB[2][16][60];
    __shared__ float sQs[128], sQo[128], sC[32];

    const int b = blockIdx.x;
    const int t = threadIdx.x;

    // ---- folded finalizers ----
    if (t < 128) {
        double inv = 1.0 / NQKV;
        double m = g_qsum[t] * inv;
        double v = g_qsq[t] * inv - m * m;
        float sc = qg[t] * rsqrtf((float)v + EPSBN);
        sQs[t] = sc;
        sQo[t] = qb[t] - (float)m * sc;
    } else if (t < 136) {
        int g = t - 128;
        double inv = 1.0 / NSIM;
        float fac[3] = {1.f, 0.1f, 0.1f};
        float csum = 0.f;
        for (int r = 0; r < 3; ++r) {
            int idx = r * 8 + g;
            double m = g_ssum[idx] * inv;
            double v = g_ssq[idx] * inv - m * m;
            float aa = sg[idx] * rsqrtf((float)v + EPSBN);
            sC[4 * g + r] = aa * fac[r];
            csum += sb[idx] - (float)m * aa;
        }
        sC[4 * g + 3] = csum;
    }
    // ---- rel tables (once per block) ----
    for (int idx = t; idx < 8 * 111; idx += 448) {
        int c = idx / 111, d = idx % 111;
        if (c < 4) relQK[d][c] = __float2half(relative[c * 111 + d]);
        else       relQK[d][c] = __float2half(relative[c * 111 + (110 - d)]);
    }
    for (int idx = t; idx < 8 * 111; idx += 448) {
        int c = idx / 111, d = idx % 111;
        relV[d][c] = __float2half(relative[(8 + c) * 111 + d]);
    }
    __syncthreads();

    // ---- stage all 128 BN'd channels via float4 loads ----
    {
        const float* src = g_qkv + (size_t)b * CH_STR;
        const int chq = t / 14, i4 = t % 14;   // 32 channels x 14 float4 per iter
#pragma unroll
        for (int it = 0; it < 4; ++it) {
            int ch = it * 32 + chq;
            float4 v = *(const float4*)&src[ch * 56 + i4 * 4];
            float sc = sQs[ch], of = sQo[ch];
            float vals[4] = {v.x * sc + of, v.y * sc + of, v.z * sc + of, v.w * sc + of};
            int g = ch >> 4, cc = ch & 15;
#pragma unroll
            for (int e = 0; e < 4; ++e) {
                int i = i4 * 4 + e;
                if (cc < 4) qsT[g][i][cc] = vals[e];
                else if (cc < 8) ksT[g][i][cc - 4] = vals[e];
                else vsT[g][i][cc - 8] = vals[e];
            }
        }
    }
    __syncthreads();

    const int lane = t & 31;
    const int h  = lane & 1;
    const int tj = (lane >> 1) & 7;
    const int igp = lane >> 4;
    const int ti = (t >> 5) * 2 + igp;     // 14 warps x 2 = 0..27
    const int i0 = ti * 2, j0 = tj * 7;
    const int dbase = i0 - j0 + 49;
    const int chown = ((tj & 1) << 2) | (tj & 2) | ((tj >> 2) & 1);  // bitrev3(tj)

#pragma unroll 1
    for (int gp = 0; gp < 4; ++gp) {
        const int g = gp * 2 + h;
        const float cqk = sC[4 * g], cqr = sC[4 * g + 1], ckr = sC[4 * g + 2], soff = sC[4 * g + 3];

        float4 q0v = *(const float4*)qsT[g][i0];
        float4 q1v = *(const float4*)qsT[g][i0 + 1];

        // ---- phase 1: logits by diagonals, rolling k, deduped fp16 rel ----
        float P[14];
        {
            float4 kcur, kprev;
#pragma unroll
            for (int cc = 0; cc < 8; ++cc) {
                int d = dbase + cc;
                uint4 rw = *(const uint4*)relQK[d];
                const __half2* hp = (const __half2*)&rw;
                float2 ra = __half22float2(hp[0]);
                float2 rb = __half22float2(hp[1]);
                float2 rc = __half22float2(hp[2]);
                float2 rd = __half22float2(hp[3]);
                if (cc <= 6) {
                    kcur = *(const float4*)ksT[g][j0 + 6 - cc];
                    float qk = q0v.x * kcur.x + q0v.y * kcur.y + q0v.z * kcur.z + q0v.w * kcur.w;
                    float qr = q0v.x * ra.x + q0v.y * ra.y + q0v.z * rb.x + q0v.w * rb.y;
                    float kr = kcur.x * rc.x + kcur.y * rc.y + kcur.z * rd.x + kcur.w * rd.y;
                    P[6 - cc] = fmaf(cqk, qk, fmaf(cqr, qr, fmaf(ckr, kr, soff)));
                }
                if (cc >= 1) {
                    float qk = q1v.x * kprev.x + q1v.y * kprev.y + q1v.z * kprev.z + q1v.w * kprev.w;
                    float qr = q1v.x * ra.x + q1v.y * ra.y + q1v.z * rb.x + q1v.w * rb.y;
                    float kr = kprev.x * rc.x + kprev.y * rc.y + kprev.z * rd.x + kprev.w * rd.y;
                    P[7 + 7 - cc] = fmaf(cqk, qk, fmaf(cqr, qr, fmaf(ckr, kr, soff)));
                }
                kprev = kcur;
            }
        }

        // ---- phase 2: exp + butterfly row sums over tj (masks 2,4,8) ----
        float rinv0, rinv1;
        {
            float rs0 = 0.f, rs1 = 0.f;
#pragma unroll
            for (int jj = 0; jj < 7; ++jj) {
                float p0 = __expf(P[jj]);
                float p1 = __expf(P[7 + jj]);
                P[jj] = p0; P[7 + jj] = p1;
                rs0 += p0; rs1 += p1;
            }
#pragma unroll
            for (int m = 2; m < 16; m <<= 1) {
                rs0 += __shfl_xor_sync(0xffffffffu, rs0, m);
                rs1 += __shfl_xor_sync(0xffffffffu, rs1, m);
            }
            rinv0 = 1.0f / rs0;
            rinv1 = 1.0f / rs1;
        }

        // ---- phase 3a: sv partials + reduce-scatter ----
        {
            float av[16];
#pragma unroll
            for (int v = 0; v < 16; ++v) av[v] = 0.f;
#pragma unroll
            for (int jj = 0; jj < 7; ++jj) {
                float4 v0 = *(const float4*)&vsT[g][j0 + jj][0];
                float4 v1 = *(const float4*)&vsT[g][j0 + jj][4];
                float p0 = P[jj], p1 = P[7 + jj];
                av[0] += p0 * v0.x; av[1] += p1 * v0.x;
                av[2] += p0 * v0.y; av[3] += p1 * v0.y;
                av[4] += p0 * v0.z; av[5] += p1 * v0.z;
                av[6] += p0 * v0.w; av[7] += p1 * v0.w;
                av[8]  += p0 * v1.x; av[9]  += p1 * v1.x;
                av[10] += p0 * v1.y; av[11] += p1 * v1.y;
                av[12] += p0 * v1.z; av[13] += p1 * v1.z;
                av[14] += p0 * v1.w; av[15] += p1 * v1.w;
            }
            float s0, s1;
            reduce_scatter16p(av, tj, s0, s1);
            SB[h][2 * chown][i0]     = s0 * rinv0;
            SB[h][2 * chown][i0 + 1] = s1 * rinv1;
        }

        // ---- phase 3b: sve partials (deduped fp16 relV) + reduce-scatter ----
        {
            float av[16];
#pragma unroll
            for (int v = 0; v < 16; ++v) av[v] = 0.f;
#pragma unroll
            for (int cc = 0; cc < 8; ++cc) {
                int d = dbase + cc;
                uint4 rw = *(const uint4*)relV[d];
                const __half2* hp = (const __half2*)&rw;
                float2 va = __half22float2(hp[0]);
                float2 vb = __half22float2(hp[1]);
                float2 vc = __half22float2(hp[2]);
                float2 vd = __half22float2(hp[3]);
                if (cc <= 6) {
                    float p = P[6 - cc];
                    av[0] += p * va.x; av[2]  += p * va.y; av[4]  += p * vb.x; av[6]  += p * vb.y;
                    av[8] += p * vc.x; av[10] += p * vc.y; av[12] += p * vd.x; av[14] += p * vd.y;
                }
                if (cc >= 1) {
                    float p = P[7 + 7 - cc];
                    av[1] += p * va.x; av[3]  += p * va.y; av[5]  += p * vb.x; av[7]  += p * vb.y;
                    av[9] += p * vc.x; av[11] += p * vc.y; av[13] += p * vd.x; av[15] += p * vd.y;
                }
            }
            float s0, s1;
            reduce_scatter16p(av, tj, s0, s1);
            SB[h][2 * chown + 1][i0]     = s0 * rinv0 * 0.1f;
            SB[h][2 * chown + 1][i0 + 1] = s1 * rinv1 * 0.1f;
        }
        __syncthreads();

        // ---- coalesced float4 write to g_so (both heads) ----
        {
            int hh = t / 224;
            int rem = t % 224;
            int row = rem / 14, c4 = rem % 14;
            float4 v4 = *(const float4*)&SB[hh][row][c4 * 4];
            float* ob = g_so + (size_t)b * CH_STR + (gp * 2 + hh) * 16 * 56;
            *(float4*)&ob[row * 56 + c4 * 4] = v4;
        }

        // ---- out stats: 256 threads = 2 heads x 16 rows x 8 lanes ----
        if (t < 256) {
            int hh = t >> 7, row = (t >> 3) & 15, sub = t & 7;
            float s1 = 0.f, s2 = 0.f;
#pragma unroll
            for (int e = 0; e < 7; ++e) {
                float v = SB[hh][row][sub * 7 + e];
                s1 += v; s2 += v * v;
            }
#pragma unroll
            for (int m = 1; m < 8; m <<= 1) {
                s1 += __shfl_xor_sync(0xffffffffu, s1, m);
                s2 += __shfl_xor_sync(0xffffffffu, s2, m);
            }
            if (sub == 0) {
                atomicAdd(&g_osum[(gp * 2 + hh) * 16 + row], (double)s1);
                atomicAdd(&g_osq [(gp * 2 + hh) * 16 + row], (double)s2);
            }
        }
        __syncthreads();   // SB consumed; safe for next head pair
    }
}

// ---------------- K4: out BN (folded finalize) + pair-sum + layout ----------
__global__ void __launch_bounds__(256) k_out(float* __restrict__ out,
                                             const float* __restrict__ og,
                                             const float* __restrict__ ob) {
    __shared__ float sOs[128], sOo[128];
    {
        int o = threadIdx.x;
        if (o < 128) {
            double inv = 1.0 / NQKV;
            double m = g_osum[o] * inv;
            double v = g_osq[o] * inv - m * m;
            float sc = og[o] * rsqrtf((float)v + EPSBN);
            sOs[o] = sc;
            sOo[o] = ob[o] - (float)m * sc;
        }
    }
    __syncthreads();
    int idx = blockIdx.x * 256 + threadIdx.x;
    if (idx >= 1605632) return;
    int e  = idx * 4;
    int cp = e / XPLANE;
    int r  = e % XPLANE;
    int bq = r / 56, i = r % 56;
    const float* base = g_so + (size_t)bq * CH_STR + (2 * cp) * 56 + i;
    float4 s0 = *(const float4*)base;
    float4 s1 = *(const float4*)(base + 56);
    float sc0 = sOs[2 * cp], of0 = sOo[2 * cp];
    float sc1 = sOs[2 * cp + 1], of1 = sOo[2 * cp + 1];
    float4 o4;
    o4.x = s0.x * sc0 + of0 + s1.x * sc1 + of1;
    o4.y = s0.y * sc0 + of0 + s1.y * sc1 + of1;
    o4.z = s0.z * sc0 + of0 + s1.z * sc1 + of1;
    o4.w = s0.w * sc0 + of0 + s1.w * sc1 + of1;
    *(float4*)&out[e] = o4;
}

// ---------------- launch -----------------------------------------------------
extern "C" void kernel_launch(void* const* d_in, const int* in_sizes, int n_in,
                              void* d_out, int out_size) {
    const float* x        = (const float*)d_in[0];
    const float* w_qkv    = (const float*)d_in[1];
    const float* relative = (const float*)d_in[2];
    const float* qg       = (const float*)d_in[3];
    const float* qb       = (const float*)d_in[4];
    const float* sg       = (const float*)d_in[5];
    const float* sb       = (const float*)d_in[6];
    const float* og       = (const float*)d_in[7];
    const float* ob       = (const float*)d_in[8];
    float* out            = (float*)d_out;

    k_init <<<1, 256>>>(relative);
    k_qkv  <<<BTOT, 256>>>(x, w_qkv);
    k_mom  <<<BTOT, 256>>>(qg, qb);
    k_attn <<<BTOT, 448>>>(relative, qg, qb, sg, sb);
    k_out  <<<6272, 256>>>(out, og, ob);
}

// round 10
// speedup vs baseline: 1.5167x; 1.5167x over previous
#include <cuda_runtime.h>
#include <cuda_fp16.h>
#include <math.h>

// Problem constants
#define BTOT   1792          // N*D*H = 1*32*56
#define CH_STR 7168          // 128*56
#define XPLANE 100352        // 32*56*56 == BTOT*56
#define NQKV   100352.0
#define NSIM   5619712.0     // BTOT*56*56
#define EPSBN  1e-5f

// ---------------- scratch (device globals; no runtime alloc) ----------------
__device__ float g_qkv[BTOT * 128 * 56];   // [b][o][i]  o = g*16+cc (q:0-3,k:4-7,v:8-15)
__device__ float g_so [BTOT * 128 * 56];   // [b][o2][i]
__device__ double g_qsum[128], g_qsq[128];
__device__ double g_ssum[24],  g_ssq[24];
__device__ double g_osum[128], g_osq[128];
// precomputed relative-embedding moment tables
__device__ float g_SR[8][56];
__device__ float g_TQ[10][56];
__device__ float g_TK[10][56];

__constant__ int   c_PA[10] = {0,0,0,0,1,1,1,2,2,3};
__constant__ int   c_PB[10] = {0,1,2,3,1,2,3,2,3,3};
__constant__ float c_PW[10] = {1.f,2.f,2.f,2.f,1.f,2.f,2.f,1.f,2.f,1.f};

// ---------------- K_init: zero accumulators + prefix tables -----------------
__global__ void k_init(const float* __restrict__ relative) {
    __shared__ float rel[8][112];
    int t = threadIdx.x;
    if (t < 128) { g_qsum[t] = 0.0; g_qsq[t] = 0.0; g_osum[t] = 0.0; g_osq[t] = 0.0; }
    if (t < 24)  { g_ssum[t] = 0.0; g_ssq[t] = 0.0; }
    for (int idx = t; idx < 8 * 111; idx += 256)
        rel[idx / 111][idx % 111] = relative[idx];
    __syncthreads();
    for (int task = t; task < 448; task += 256) {
        int c = task / 56, i = task % 56;
        float s = 0.f;
        for (int d = 0; d < 56; ++d) s += rel[c][i + d];
        g_SR[c][i] = s;
    }
    for (int task = t; task < 1120; task += 256) {
        int p = task / 56, i = task % 56;
        int pp = p % 10; int isK = (p >= 10) ? 4 : 0;
        int a = c_PA[pp] + isK, bb = c_PB[pp] + isK;
        float s = 0.f;
        for (int d = 0; d < 56; ++d) s += rel[a][i + d] * rel[bb][i + d];
        s *= c_PW[pp];
        if (isK) g_TK[pp][i] = s; else g_TQ[pp][i] = s;
    }
}

// ---------------- K1: qkv = w @ x  (8ch x 7pos tiles, vectorized) -----------
__global__ void __launch_bounds__(128) k_qkv(const float* __restrict__ x,
                                             const float* __restrict__ w) {
    __shared__ __align__(16) float xs[64][60];    // [c][i], row 240B (16B aligned)
    __shared__ __align__(16) float wsT[64][132];  // [c][o], transposed weights
    const int b = blockIdx.x;
    const int t = threadIdx.x;

    // x rows: 56 contiguous floats, b*56 elem offset is 16B aligned
    for (int idx = t; idx < 64 * 14; idx += 128) {
        int c = idx / 14, q4 = idx % 14;
        *(float4*)&xs[c][q4 * 4] = *(const float4*)&x[c * XPLANE + b * 56 + q4 * 4];
    }
    // transpose w[o][c] -> wsT[c][o]
    for (int idx = t; idx < 128 * 64; idx += 128) {
        int o = idx >> 6, c = idx & 63;
        wsT[c][o] = w[idx];
    }
    __syncthreads();

    const int og = t >> 3;                 // 0..15  (8 output channels each)
    const int ig = t & 7;                  // 0..7   (7 positions each)
    const int o0 = og * 8, i0 = ig * 7;
    float acc[8][7];
#pragma unroll
    for (int a = 0; a < 8; a++)
#pragma unroll
        for (int c2 = 0; c2 < 7; c2++) acc[a][c2] = 0.f;

    for (int c = 0; c < 64; ++c) {
        float4 wa = *(const float4*)&wsT[c][o0];
        float4 wb = *(const float4*)&wsT[c][o0 + 4];
        float xv[7];
#pragma unroll
        for (int ii = 0; ii < 7; ++ii) xv[ii] = xs[c][i0 + ii];
#pragma unroll
        for (int ii = 0; ii < 7; ++ii) {
            acc[0][ii] += wa.x * xv[ii]; acc[1][ii] += wa.y * xv[ii];
            acc[2][ii] += wa.z * xv[ii]; acc[3][ii] += wa.w * xv[ii];
            acc[4][ii] += wb.x * xv[ii]; acc[5][ii] += wb.y * xv[ii];
            acc[6][ii] += wb.z * xv[ii]; acc[7][ii] += wb.w * xv[ii];
        }
    }
    float* outb = g_qkv + (size_t)b * CH_STR;
#pragma unroll
    for (int oo = 0; oo < 8; ++oo) {
        float s = 0.f, sq = 0.f;
#pragma unroll
        for (int ii = 0; ii < 7; ++ii) {
            float v = acc[oo][ii];
            outb[(o0 + oo) * 56 + i0 + ii] = v;
            s += v; sq += v * v;
        }
        // reduce over the 8 ig-lanes (lane bits 0..2)
        for (int off = 4; off; off >>= 1) {
            s  += __shfl_down_sync(0xffffffffu, s,  off);
            sq += __shfl_down_sync(0xffffffffu, sq, off);
        }
        if (ig == 0) {
            atomicAdd(&g_qsum[o0 + oo], (double)s);
            atomicAdd(&g_qsq [o0 + oo], (double)sq);
        }
    }
}

// ---------------- K2: analytic sim moments (folds qkv-BN finalize) ----------
__global__ void __launch_bounds__(256) k_mom(const float* __restrict__ qg,
                                             const float* __restrict__ qb) {
    __shared__ float sQs[128], sQo[128];
    const int b = blockIdx.x;
    {
        int o = threadIdx.x;
        if (o < 128) {
            double inv = 1.0 / NQKV;
            double m = g_qsum[o] * inv;
            double v = g_qsq[o] * inv - m * m;
            float sc = qg[o] * rsqrtf((float)v + EPSBN);
            sQs[o] = sc;
            sQo[o] = qb[o] - (float)m * sc;
        }
    }
    __syncthreads();

    const int g = threadIdx.x >> 5;
    const int lane = threadIdx.x & 31;
    const float* base = g_qkv + (size_t)b * CH_STR + g * 16 * 56;

    float part[32];
#pragma unroll
    for (int v = 0; v < 32; ++v) part[v] = 0.f;

#pragma unroll
    for (int ii = 0; ii < 2; ++ii) {
        int i = lane + ii * 32;
        if (i < 56) {
            float q[4], k[4];
#pragma unroll
            for (int c = 0; c < 4; ++c) {
                int oq = g * 16 + c, ok = g * 16 + 4 + c;
                q[c] = base[c * 56 + i]       * sQs[oq] + sQo[oq];
                k[c] = base[(4 + c) * 56 + i] * sQs[ok] + sQo[ok];
            }
#pragma unroll
            for (int c = 0; c < 4; ++c) {
                part[c]     += q[c];
                part[4 + c] += k[c];
                part[28] += q[c] * g_SR[c][i];
                part[30] += k[c] * g_SR[4 + c][i];
            }
#pragma unroll
            for (int p = 0; p < 10; ++p) {
                float pq = q[c_PA[p]] * q[c_PB[p]];
                float pk = k[c_PA[p]] * k[c_PB[p]];
                part[8 + p]  += pq;
                part[18 + p] += pk;
                part[29] += pq * g_TQ[p][i];
                part[31] += pk * g_TK[p][i];
            }
        }
    }
#pragma unroll
    for (int v = 0; v < 32; ++v)
        for (int off = 16; off; off >>= 1)
            part[v] += __shfl_down_sync(0xffffffffu, part[v], off);

    if (lane == 0) {
        float S1 = 0.f, S2 = 0.f;
#pragma unroll
        for (int c = 0; c < 4; ++c) S1 += part[c] * part[4 + c];
#pragma unroll
        for (int p = 0; p < 10; ++p) S2 += c_PW[p] * part[8 + p] * part[18 + p];
        atomicAdd(&g_ssum[g],      (double)S1);
        atomicAdd(&g_ssq [g],      (double)S2);
        atomicAdd(&g_ssum[8 + g],  (double)(0.1f  * part[28]));
        atomicAdd(&g_ssq [8 + g],  (double)(0.01f * part[29]));
        atomicAdd(&g_ssum[16 + g], (double)(0.1f  * part[30]));
        atomicAdd(&g_ssq [16 + g], (double)(0.01f * part[31]));
    }
}

// ---- warp reduce-scatter: 16 partials spread over 8 consecutive lanes ------
__device__ __forceinline__ void reduce_scatter16(const float* av, int tj,
                                                 float& o0, float& o1) {
    float a8[8];
#pragma unroll
    for (int v = 0; v < 8; ++v) {
        float snd = (tj & 1) ? av[v] : av[8 + v];
        float kp  = (tj & 1) ? av[8 + v] : av[v];
        a8[v] = kp + __shfl_xor_sync(0xffffffffu, snd, 1);
    }
    float a4[4];
#pragma unroll
    for (int v = 0; v < 4; ++v) {
        float snd = (tj & 2) ? a8[v] : a8[4 + v];
        float kp  = (tj & 2) ? a8[4 + v] : a8[v];
        a4[v] = kp + __shfl_xor_sync(0xffffffffu, snd, 2);
    }
    float a2[2];
#pragma unroll
    for (int v = 0; v < 2; ++v) {
        float snd = (tj & 4) ? a4[v] : a4[2 + v];
        float kp  = (tj & 4) ? a4[2 + v] : a4[v];
        a2[v] = kp + __shfl_xor_sync(0xffffffffu, snd, 4);
    }
    o0 = a2[0]; o1 = a2[1];
}

// ---------------- K3: attention — block = b, loop over 8 heads (R8) ---------
// 224 threads. warp w, lane l: tj = l&7, ig = l>>3, ti = w*4+ig (0..27),
// rows i0=2ti, i0+1; cols j0=7tj..7tj+6. Rel tables loaded ONCE per block.
__global__ void __launch_bounds__(224, 5) k_attn(const float* __restrict__ relative,
                                                 const float* __restrict__ qg,
                                                 const float* __restrict__ qb,
                                                 const float* __restrict__ sg,
                                                 const float* __restrict__ sb) {
    __shared__ __align__(16) float qsT[8][56][4];
    __shared__ __align__(16) float ksT[8][56][4];
    __shared__ __align__(16) float vsT[8][56][8];
    __shared__ __align__(16) __half relQK[111][8];  // {relq[0..3][d], relk[0..3][110-d]}
    __shared__ __align__(16) __half relV[111][8];   // {relv[0..7][d]}
    __shared__ __align__(16) float SB[16][60];
    __shared__ float sQs[128], sQo[128], sC[32];

    const int b = blockIdx.x;
    const int t = threadIdx.x;

    // ---- folded finalizers: all 128 qkv-BN channels + 8 heads' sim coeffs --
    if (t < 128) {
        double inv = 1.0 / NQKV;
        double m = g_qsum[t] * inv;
        double v = g_qsq[t] * inv - m * m;
        float sc = qg[t] * rsqrtf((float)v + EPSBN);
        sQs[t] = sc;
        sQo[t] = qb[t] - (float)m * sc;
    } else if (t < 136) {
        int g = t - 128;
        double inv = 1.0 / NSIM;
        float fac[3] = {1.f, 0.1f, 0.1f};
        float csum = 0.f;
        for (int r = 0; r < 3; ++r) {
            int idx = r * 8 + g;
            double m = g_ssum[idx] * inv;
            double v = g_ssq[idx] * inv - m * m;
            float aa = sg[idx] * rsqrtf((float)v + EPSBN);
            sC[4 * g + r] = aa * fac[r];
            csum += sb[idx] - (float)m * aa;
        }
        sC[4 * g + 3] = csum;
    }
    // ---- rel tables (once per block) ----
    for (int idx = t; idx < 8 * 111; idx += 224) {
        int c = idx / 111, d = idx % 111;
        if (c < 4) relQK[d][c] = __float2half(relative[c * 111 + d]);
        else       relQK[d][c] = __float2half(relative[c * 111 + (110 - d)]);
    }
    for (int idx = t; idx < 8 * 111; idx += 224) {
        int c = idx / 111, d = idx % 111;
        relV[d][c] = __float2half(relative[(8 + c) * 111 + d]);
    }
    __syncthreads();

    // ---- stage all 128 BN'd channels via float4 loads ----
    {
        const float* src = g_qkv + (size_t)b * CH_STR;
        const int chr = t / 14, i4 = t % 14;   // 16 channels x 14 float4 per iter
#pragma unroll
        for (int it = 0; it < 8; ++it) {
            int ch = it * 16 + chr;
            float4 v = *(const float4*)&src[ch * 56 + i4 * 4];
            float sc = sQs[ch], of = sQo[ch];
            float vals[4] = {v.x * sc + of, v.y * sc + of, v.z * sc + of, v.w * sc + of};
            int g = ch >> 4, cc = ch & 15;
#pragma unroll
            for (int e = 0; e < 4; ++e) {
                int i = i4 * 4 + e;
                if (cc < 4) qsT[g][i][cc] = vals[e];
                else if (cc < 8) ksT[g][i][cc - 4] = vals[e];
                else vsT[g][i][cc - 8] = vals[e];
            }
        }
    }
    __syncthreads();

    const int lane = t & 31;
    const int tj = lane & 7, ig = lane >> 3;
    const int ti = (t >> 5) * 4 + ig;
    const int i0 = ti * 2, j0 = tj * 7;
    const int dbase = i0 - j0 + 49;
    const int chown = ((tj & 1) << 2) | (tj & 2) | ((tj >> 2) & 1);  // bitrev3(tj)
    const int row_w = t / 14, c4_w = t % 14;   // g_so write mapping

#pragma unroll 1
    for (int g = 0; g < 8; ++g) {
        const float cqk = sC[4 * g], cqr = sC[4 * g + 1], ckr = sC[4 * g + 2], soff = sC[4 * g + 3];

        float4 q0v = *(const float4*)qsT[g][i0];
        float4 q1v = *(const float4*)qsT[g][i0 + 1];

        // ---- phase 1: logits by diagonals, rolling k, fused fp16 rel row ----
        float P[14];
        {
            float4 kcur, kprev;
#pragma unroll
            for (int cc = 0; cc < 8; ++cc) {
                int d = dbase + cc;
                uint4 rw = *(const uint4*)relQK[d];
                const __half2* hp = (const __half2*)&rw;
                float2 ra = __half22float2(hp[0]);
                float2 rb = __half22float2(hp[1]);
                float2 rc = __half22float2(hp[2]);
                float2 rd = __half22float2(hp[3]);
                if (cc <= 6) {
                    kcur = *(const float4*)ksT[g][j0 + 6 - cc];
                    float qk = q0v.x * kcur.x + q0v.y * kcur.y + q0v.z * kcur.z + q0v.w * kcur.w;
                    float qr = q0v.x * ra.x + q0v.y * ra.y + q0v.z * rb.x + q0v.w * rb.y;
                    float kr = kcur.x * rc.x + kcur.y * rc.y + kcur.z * rd.x + kcur.w * rd.y;
                    P[6 - cc] = fmaf(cqk, qk, fmaf(cqr, qr, fmaf(ckr, kr, soff)));
                }
                if (cc >= 1) {
                    float qk = q1v.x * kprev.x + q1v.y * kprev.y + q1v.z * kprev.z + q1v.w * kprev.w;
                    float qr = q1v.x * ra.x + q1v.y * ra.y + q1v.z * rb.x + q1v.w * rb.y;
                    float kr = kprev.x * rc.x + kprev.y * rc.y + kprev.z * rd.x + kprev.w * rd.y;
                    P[7 + 7 - cc] = fmaf(cqk, qk, fmaf(cqr, qr, fmaf(ckr, kr, soff)));
                }
                kprev = kcur;
            }
        }

        // ---- phase 2: exp + warp-butterfly row sums ----
        float rinv0, rinv1;
        {
            float rs0 = 0.f, rs1 = 0.f;
#pragma unroll
            for (int jj = 0; jj < 7; ++jj) {
                float p0 = __expf(P[jj]);
                float p1 = __expf(P[7 + jj]);
                P[jj] = p0; P[7 + jj] = p1;
                rs0 += p0; rs1 += p1;
            }
#pragma unroll
            for (int m = 1; m < 8; m <<= 1) {
                rs0 += __shfl_xor_sync(0xffffffffu, rs0, m);
                rs1 += __shfl_xor_sync(0xffffffffu, rs1, m);
            }
            rinv0 = 1.0f / rs0;
            rinv1 = 1.0f / rs1;
        }

        // ---- phase 3a: sv partials + warp reduce-scatter ----
        {
            float av[16];
#pragma unroll
            for (int v = 0; v < 16; ++v) av[v] = 0.f;
#pragma unroll
            for (int jj = 0; jj < 7; ++jj) {
                float4 v0 = *(const float4*)&vsT[g][j0 + jj][0];
                float4 v1 = *(const float4*)&vsT[g][j0 + jj][4];
                float p0 = P[jj], p1 = P[7 + jj];
                av[0] += p0 * v0.x; av[1] += p1 * v0.x;
                av[2] += p0 * v0.y; av[3] += p1 * v0.y;
                av[4] += p0 * v0.z; av[5] += p1 * v0.z;
                av[6] += p0 * v0.w; av[7] += p1 * v0.w;
                av[8]  += p0 * v1.x; av[9]  += p1 * v1.x;
                av[10] += p0 * v1.y; av[11] += p1 * v1.y;
                av[12] += p0 * v1.z; av[13] += p1 * v1.z;
                av[14] += p0 * v1.w; av[15] += p1 * v1.w;
            }
            float s0, s1;
            reduce_scatter16(av, tj, s0, s1);
            SB[2 * chown][i0]     = s0 * rinv0;
            SB[2 * chown][i0 + 1] = s1 * rinv1;
        }

        // ---- phase 3b: sve partials (fp16 relv rows) + reduce-scatter ----
        {
            float av[16];
#pragma unroll
            for (int v = 0; v < 16; ++v) av[v] = 0.f;
#pragma unroll
            for (int cc = 0; cc < 8; ++cc) {
                int d = dbase + cc;
                uint4 rw = *(const uint4*)relV[d];
                const __half2* hp = (const __half2*)&rw;
                float2 va = __half22float2(hp[0]);
                float2 vb = __half22float2(hp[1]);
                float2 vc = __half22float2(hp[2]);
                float2 vd = __half22float2(hp[3]);
                if (cc <= 6) {
                    float p = P[6 - cc];
                    av[0] += p * va.x; av[2]  += p * va.y; av[4]  += p * vb.x; av[6]  += p * vb.y;
                    av[8] += p * vc.x; av[10] += p * vc.y; av[12] += p * vd.x; av[14] += p * vd.y;
                }
                if (cc >= 1) {
                    float p = P[7 + 7 - cc];
                    av[1] += p * va.x; av[3]  += p * va.y; av[5]  += p * vb.x; av[7]  += p * vb.y;
                    av[9] += p * vc.x; av[11] += p * vc.y; av[13] += p * vd.x; av[15] += p * vd.y;
                }
            }
            float s0, s1;
            reduce_scatter16(av, tj, s0, s1);
            SB[2 * chown + 1][i0]     = s0 * rinv0 * 0.1f;
            SB[2 * chown + 1][i0 + 1] = s1 * rinv1 * 0.1f;
        }
        __syncthreads();

        // ---- coalesced float4 write to g_so for this head ----
        {
            float4 v4 = *(const float4*)&SB[row_w][c4_w * 4];
            float* ob = g_so + (size_t)b * CH_STR + g * 16 * 56;
            *(float4*)&ob[row_w * 56 + c4_w * 4] = v4;
        }

        // ---- out stats: 128 threads = 16 rows x 8 lanes, butterfly reduce ----
        if (t < 128) {
            int row = t >> 3, sub = t & 7;
            float s1 = 0.f, s2 = 0.f;
#pragma unroll
            for (int e = 0; e < 7; ++e) {
                float v = SB[row][sub * 7 + e];
                s1 += v; s2 += v * v;
            }
#pragma unroll
            for (int m = 1; m < 8; m <<= 1) {
                s1 += __shfl_xor_sync(0xffffffffu, s1, m);
                s2 += __shfl_xor_sync(0xffffffffu, s2, m);
            }
            if (sub == 0) {
                atomicAdd(&g_osum[g * 16 + row], (double)s1);
                atomicAdd(&g_osq [g * 16 + row], (double)s2);
            }
        }
        __syncthreads();   // SB consumed; safe for next head
    }
}

// ---------------- K4: out BN (folded finalize) + pair-sum + layout ----------
__global__ void __launch_bounds__(256) k_out(float* __restrict__ out,
                                             const float* __restrict__ og,
                                             const float* __restrict__ ob) {
    __shared__ float sOs[128], sOo[128];
    {
        int o = threadIdx.x;
        if (o < 128) {
            double inv = 1.0 / NQKV;
            double m = g_osum[o] * inv;
            double v = g_osq[o] * inv - m * m;
            float sc = og[o] * rsqrtf((float)v + EPSBN);
            sOs[o] = sc;
            sOo[o] = ob[o] - (float)m * sc;
        }
    }
    __syncthreads();
    int idx = blockIdx.x * 256 + threadIdx.x;
    if (idx >= 1605632) return;
    int e  = idx * 4;
    int cp = e / XPLANE;
    int r  = e % XPLANE;
    int bq = r / 56, i = r % 56;
    const float* base = g_so + (size_t)bq * CH_STR + (2 * cp) * 56 + i;
    float4 s0 = *(const float4*)base;
    float4 s1 = *(const float4*)(base + 56);
    float sc0 = sOs[2 * cp], of0 = sOo[2 * cp];
    float sc1 = sOs[2 * cp + 1], of1 = sOo[2 * cp + 1];
    float4 o4;
    o4.x = s0.x * sc0 + of0 + s1.x * sc1 + of1;
    o4.y = s0.y * sc0 + of0 + s1.y * sc1 + of1;
    o4.z = s0.z * sc0 + of0 + s1.z * sc1 + of1;
    o4.w = s0.w * sc0 + of0 + s1.w * sc1 + of1;
    *(float4*)&out[e] = o4;
}

// ---------------- launch -----------------------------------------------------
extern "C" void kernel_launch(void* const* d_in, const int* in_sizes, int n_in,
                              void* d_out, int out_size) {
    const float* x        = (const float*)d_in[0];
    const float* w_qkv    = (const float*)d_in[1];
    const float* relative = (const float*)d_in[2];
    const float* qg       = (const float*)d_in[3];
    const float* qb       = (const float*)d_in[4];
    const float* sg       = (const float*)d_in[5];
    const float* sb       = (const float*)d_in[6];
    const float* og       = (const float*)d_in[7];
    const float* ob       = (const float*)d_in[8];
    float* out            = (float*)d_out;

    k_init <<<1, 256>>>(relative);
    k_qkv  <<<BTOT, 128>>>(x, w_qkv);
    k_mom  <<<BTOT, 256>>>(qg, qb);
    k_attn <<<BTOT, 224>>>(relative, qg, qb, sg, sb);
    k_out  <<<6272, 256>>>(out, og, ob);
}

// round 11
// speedup vs baseline: 1.6196x; 1.0678x over previous
#include <cuda_runtime.h>
#include <cuda_fp16.h>
#include <math.h>

// Problem constants
#define BTOT   1792          // N*D*H = 1*32*56
#define CH_STR 7168          // 128*56
#define XPLANE 100352        // 32*56*56 == BTOT*56
#define NQKV   100352.0
#define NSIM   5619712.0     // BTOT*56*56
#define EPSBN  1e-5f

typedef unsigned long long u64t;

// ---- packed fp32x2 helpers (sm_103a dual-fp32; lanewise IEEE fp32) ---------
__device__ __forceinline__ u64t pack2(float lo, float hi) {
    u64t d; asm("mov.b64 %0, {%1, %2};" : "=l"(d) : "f"(lo), "f"(hi)); return d;
}
__device__ __forceinline__ float2 unpack2(u64t d) {
    float2 r; asm("mov.b64 {%0, %1}, %2;" : "=f"(r.x), "=f"(r.y) : "l"(d)); return r;
}
__device__ __forceinline__ u64t ffma2(u64t a, u64t b, u64t c) {
    u64t d; asm("fma.rn.f32x2 %0, %1, %2, %3;" : "=l"(d) : "l"(a), "l"(b), "l"(c));
    return d;
}

// ---------------- scratch (device globals; no runtime alloc) ----------------
__device__ float  g_qkv[BTOT * 128 * 56];  // [b][o][i]  o = g*16+cc
__device__ __half g_so [BTOT * 128 * 56];  // [b][o2][i] fp16 (stats kept fp32)
__device__ double g_qsum[128], g_qsq[128];
__device__ double g_ssum[24],  g_ssq[24];
__device__ double g_osum[128], g_osq[128];
__device__ float g_SR[8][56];
__device__ float g_TQ[10][56];
__device__ float g_TK[10][56];

__constant__ int   c_PA[10] = {0,0,0,0,1,1,1,2,2,3};
__constant__ int   c_PB[10] = {0,1,2,3,1,2,3,2,3,3};
__constant__ float c_PW[10] = {1.f,2.f,2.f,2.f,1.f,2.f,2.f,1.f,2.f,1.f};

// ---------------- K_init: zero accumulators + prefix tables -----------------
__global__ void k_init(const float* __restrict__ relative) {
    __shared__ float rel[8][112];
    int t = threadIdx.x;
    if (t < 128) { g_qsum[t] = 0.0; g_qsq[t] = 0.0; g_osum[t] = 0.0; g_osq[t] = 0.0; }
    if (t < 24)  { g_ssum[t] = 0.0; g_ssq[t] = 0.0; }
    for (int idx = t; idx < 8 * 111; idx += 256)
        rel[idx / 111][idx % 111] = relative[idx];
    __syncthreads();
    for (int task = t; task < 448; task += 256) {
        int c = task / 56, i = task % 56;
        float s = 0.f;
        for (int d = 0; d < 56; ++d) s += rel[c][i + d];
        g_SR[c][i] = s;
    }
    for (int task = t; task < 1120; task += 256) {
        int p = task / 56, i = task % 56;
        int pp = p % 10; int isK = (p >= 10) ? 4 : 0;
        int a = c_PA[pp] + isK, bb = c_PB[pp] + isK;
        float s = 0.f;
        for (int d = 0; d < 56; ++d) s += rel[a][i + d] * rel[bb][i + d];
        s *= c_PW[pp];
        if (isK) g_TK[pp][i] = s; else g_TQ[pp][i] = s;
    }
}

// ---------------- K1: qkv = w @ x  (packed f32x2 FMAs) ----------------------
__global__ void __launch_bounds__(128) k_qkv(const float* __restrict__ x,
                                             const float* __restrict__ w) {
    __shared__ __align__(16) float xs[64][60];
    __shared__ __align__(16) float wsT[64][132];
    const int b = blockIdx.x;
    const int t = threadIdx.x;

    for (int idx = t; idx < 64 * 14; idx += 128) {
        int c = idx / 14, q4 = idx % 14;
        *(float4*)&xs[c][q4 * 4] = *(const float4*)&x[c * XPLANE + b * 56 + q4 * 4];
    }
    for (int idx = t; idx < 128 * 64; idx += 128) {
        int o = idx >> 6, c = idx & 63;
        wsT[c][o] = w[idx];
    }
    __syncthreads();

    const int og = t >> 3;                 // 0..15  (8 output channels each)
    const int ig = t & 7;                  // 0..7   (7 positions each)
    const int o0 = og * 8, i0 = ig * 7;
    u64t acc2[4][7];                       // channel pair (2p, 2p+1) x position
#pragma unroll
    for (int p = 0; p < 4; ++p)
#pragma unroll
        for (int ii = 0; ii < 7; ++ii) acc2[p][ii] = 0ull;

    for (int c = 0; c < 64; ++c) {
        float4 wa = *(const float4*)&wsT[c][o0];
        float4 wb = *(const float4*)&wsT[c][o0 + 4];
        u64t w01 = pack2(wa.x, wa.y), w23 = pack2(wa.z, wa.w);
        u64t w45 = pack2(wb.x, wb.y), w67 = pack2(wb.z, wb.w);
#pragma unroll
        for (int ii = 0; ii < 7; ++ii) {
            float xv = xs[c][i0 + ii];
            u64t xx = pack2(xv, xv);
            acc2[0][ii] = ffma2(w01, xx, acc2[0][ii]);
            acc2[1][ii] = ffma2(w23, xx, acc2[1][ii]);
            acc2[2][ii] = ffma2(w45, xx, acc2[2][ii]);
            acc2[3][ii] = ffma2(w67, xx, acc2[3][ii]);
        }
    }
    float* outb = g_qkv + (size_t)b * CH_STR;
#pragma unroll
    for (int p = 0; p < 4; ++p) {
        float s0 = 0.f, sq0 = 0.f, s1 = 0.f, sq1 = 0.f;
#pragma unroll
        for (int ii = 0; ii < 7; ++ii) {
            float2 u = unpack2(acc2[p][ii]);
            outb[(o0 + 2 * p) * 56 + i0 + ii]     = u.x;
            outb[(o0 + 2 * p + 1) * 56 + i0 + ii] = u.y;
            s0 += u.x; sq0 += u.x * u.x;
            s1 += u.y; sq1 += u.y * u.y;
        }
        for (int off = 4; off; off >>= 1) {
            s0  += __shfl_down_sync(0xffffffffu, s0,  off);
            sq0 += __shfl_down_sync(0xffffffffu, sq0, off);
            s1  += __shfl_down_sync(0xffffffffu, s1,  off);
            sq1 += __shfl_down_sync(0xffffffffu, sq1, off);
        }
        if (ig == 0) {
            atomicAdd(&g_qsum[o0 + 2 * p],     (double)s0);
            atomicAdd(&g_qsq [o0 + 2 * p],     (double)sq0);
            atomicAdd(&g_qsum[o0 + 2 * p + 1], (double)s1);
            atomicAdd(&g_qsq [o0 + 2 * p + 1], (double)sq1);
        }
    }
}

// ---------------- K2: analytic sim moments (folds qkv-BN finalize) ----------
__global__ void __launch_bounds__(256) k_mom(const float* __restrict__ qg,
                                             const float* __restrict__ qb) {
    __shared__ float sQs[128], sQo[128];
    const int b = blockIdx.x;
    {
        int o = threadIdx.x;
        if (o < 128) {
            double inv = 1.0 / NQKV;
            double m = g_qsum[o] * inv;
            double v = g_qsq[o] * inv - m * m;
            float sc = qg[o] * rsqrtf((float)v + EPSBN);
            sQs[o] = sc;
            sQo[o] = qb[o] - (float)m * sc;
        }
    }
    __syncthreads();

    const int g = threadIdx.x >> 5;
    const int lane = threadIdx.x & 31;
    const float* base = g_qkv + (size_t)b * CH_STR + g * 16 * 56;

    float part[32];
#pragma unroll
    for (int v = 0; v < 32; ++v) part[v] = 0.f;

#pragma unroll
    for (int ii = 0; ii < 2; ++ii) {
        int i = lane + ii * 32;
        if (i < 56) {
            float q[4], k[4];
#pragma unroll
            for (int c = 0; c < 4; ++c) {
                int oq = g * 16 + c, ok = g * 16 + 4 + c;
                q[c] = base[c * 56 + i]       * sQs[oq] + sQo[oq];
                k[c] = base[(4 + c) * 56 + i] * sQs[ok] + sQo[ok];
            }
#pragma unroll
            for (int c = 0; c < 4; ++c) {
                part[c]     += q[c];
                part[4 + c] += k[c];
                part[28] += q[c] * g_SR[c][i];
                part[30] += k[c] * g_SR[4 + c][i];
            }
#pragma unroll
            for (int p = 0; p < 10; ++p) {
                float pq = q[c_PA[p]] * q[c_PB[p]];
                float pk = k[c_PA[p]] * k[c_PB[p]];
                part[8 + p]  += pq;
                part[18 + p] += pk;
                part[29] += pq * g_TQ[p][i];
                part[31] += pk * g_TK[p][i];
            }
        }
    }
#pragma unroll
    for (int v = 0; v < 32; ++v)
        for (int off = 16; off; off >>= 1)
            part[v] += __shfl_down_sync(0xffffffffu, part[v], off);

    if (lane == 0) {
        float S1 = 0.f, S2 = 0.f;
#pragma unroll
        for (int c = 0; c < 4; ++c) S1 += part[c] * part[4 + c];
#pragma unroll
        for (int p = 0; p < 10; ++p) S2 += c_PW[p] * part[8 + p] * part[18 + p];
        atomicAdd(&g_ssum[g],      (double)S1);
        atomicAdd(&g_ssq [g],      (double)S2);
        atomicAdd(&g_ssum[8 + g],  (double)(0.1f  * part[28]));
        atomicAdd(&g_ssq [8 + g],  (double)(0.01f * part[29]));
        atomicAdd(&g_ssum[16 + g], (double)(0.1f  * part[30]));
        atomicAdd(&g_ssq [16 + g], (double)(0.01f * part[31]));
    }
}

// ---- warp reduce-scatter: 16 partials spread over 8 consecutive lanes ------
__device__ __forceinline__ void reduce_scatter16(const float* av, int tj,
                                                 float& o0, float& o1) {
    float a8[8];
#pragma unroll
    for (int v = 0; v < 8; ++v) {
        float snd = (tj & 1) ? av[v] : av[8 + v];
        float kp  = (tj & 1) ? av[8 + v] : av[v];
        a8[v] = kp + __shfl_xor_sync(0xffffffffu, snd, 1);
    }
    float a4[4];
#pragma unroll
    for (int v = 0; v < 4; ++v) {
        float snd = (tj & 2) ? a8[v] : a8[4 + v];
        float kp  = (tj & 2) ? a8[4 + v] : a8[v];
        a4[v] = kp + __shfl_xor_sync(0xffffffffu, snd, 2);
    }
    float a2[2];
#pragma unroll
    for (int v = 0; v < 2; ++v) {
        float snd = (tj & 4) ? a4[v] : a4[2 + v];
        float kp  = (tj & 4) ? a4[2 + v] : a4[v];
        a2[v] = kp + __shfl_xor_sync(0xffffffffu, snd, 4);
    }
    o0 = a2[0]; o1 = a2[1];
}

// ---------------- K3: attention — block = b, loop over 8 heads --------------
// 224 threads. warp w, lane l: tj = l&7, ig = l>>3, ti = w*4+ig (0..27),
// rows i0=2ti, i0+1; cols j0=7tj..7tj+6. Rel tables loaded ONCE per block.
// vsT padded to 12 floats/row (48B stride): conflict-free across tj lanes.
__global__ void __launch_bounds__(224, 5) k_attn(const float* __restrict__ relative,
                                                 const float* __restrict__ qg,
                                                 const float* __restrict__ qb,
                                                 const float* __restrict__ sg,
                                                 const float* __restrict__ sb) {
    __shared__ __align__(16) float qsT[8][56][4];
    __shared__ __align__(16) float ksT[8][56][4];
    __shared__ __align__(16) float vsT[8][56][12];   // 48B stride, pad
    __shared__ __align__(16) __half relQK[111][8];   // {relq[0..3][d], relk[0..3][110-d]}
    __shared__ __align__(16) __half relV[111][8];    // {relv[0..7][d]}
    __shared__ __align__(16) float SB[16][60];
    __shared__ float sQs[128], sQo[128], sC[32];

    const int b = blockIdx.x;
    const int t = threadIdx.x;

    // ---- folded finalizers: all 128 qkv-BN channels + 8 heads' sim coeffs --
    if (t < 128) {
        double inv = 1.0 / NQKV;
        double m = g_qsum[t] * inv;
        double v = g_qsq[t] * inv - m * m;
        float sc = qg[t] * rsqrtf((float)v + EPSBN);
        sQs[t] = sc;
        sQo[t] = qb[t] - (float)m * sc;
    } else if (t < 136) {
        int g = t - 128;
        double inv = 1.0 / NSIM;
        float fac[3] = {1.f, 0.1f, 0.1f};
        float csum = 0.f;
        for (int r = 0; r < 3; ++r) {
            int idx = r * 8 + g;
            double m = g_ssum[idx] * inv;
            double v = g_ssq[idx] * inv - m * m;
            float aa = sg[idx] * rsqrtf((float)v + EPSBN);
            sC[4 * g + r] = aa * fac[r];
            csum += sb[idx] - (float)m * aa;
        }
        sC[4 * g + 3] = csum;
    }
    // ---- rel tables (once per block) ----
    for (int idx = t; idx < 8 * 111; idx += 224) {
        int c = idx / 111, d = idx % 111;
        if (c < 4) relQK[d][c] = __float2half(relative[c * 111 + d]);
        else       relQK[d][c] = __float2half(relative[c * 111 + (110 - d)]);
    }
    for (int idx = t; idx < 8 * 111; idx += 224) {
        int c = idx / 111, d = idx % 111;
        relV[d][c] = __float2half(relative[(8 + c) * 111 + d]);
    }
    __syncthreads();

    // ---- stage all 128 BN'd channels via float4 loads ----
    {
        const float* src = g_qkv + (size_t)b * CH_STR;
        const int chr = t / 14, i4 = t % 14;   // 16 channels x 14 float4 per iter
#pragma unroll
        for (int it = 0; it < 8; ++it) {
            int ch = it * 16 + chr;
            float4 v = *(const float4*)&src[ch * 56 + i4 * 4];
            float sc = sQs[ch], of = sQo[ch];
            float vals[4] = {v.x * sc + of, v.y * sc + of, v.z * sc + of, v.w * sc + of};
            int g = ch >> 4, cc = ch & 15;
#pragma unroll
            for (int e = 0; e < 4; ++e) {
                int i = i4 * 4 + e;
                if (cc < 4) qsT[g][i][cc] = vals[e];
                else if (cc < 8) ksT[g][i][cc - 4] = vals[e];
                else vsT[g][i][cc - 8] = vals[e];
            }
        }
    }
    __syncthreads();

    const int lane = t & 31;
    const int tj = lane & 7, ig = lane >> 3;
    const int ti = (t >> 5) * 4 + ig;
    const int i0 = ti * 2, j0 = tj * 7;
    const int dbase = i0 - j0 + 49;
    const int chown = ((tj & 1) << 2) | (tj & 2) | ((tj >> 2) & 1);  // bitrev3(tj)
    const int row_w = t / 14, c4_w = t % 14;   // g_so write mapping

#pragma unroll 1
    for (int g = 0; g < 8; ++g) {
        const float cqk = sC[4 * g], cqr = sC[4 * g + 1], ckr = sC[4 * g + 2], soff = sC[4 * g + 3];

        float4 q0v = *(const float4*)qsT[g][i0];
        float4 q1v = *(const float4*)qsT[g][i0 + 1];

        // ---- phase 1: logits by diagonals, rolling k, fused fp16 rel row ----
        float P[14];
        {
            float4 kcur, kprev;
#pragma unroll
            for (int cc = 0; cc < 8; ++cc) {
                int d = dbase + cc;
                uint4 rw = *(const uint4*)relQK[d];
                const __half2* hp = (const __half2*)&rw;
                float2 ra = __half22float2(hp[0]);
                float2 rb = __half22float2(hp[1]);
                float2 rc = __half22float2(hp[2]);
                float2 rd = __half22float2(hp[3]);
                if (cc <= 6) {
                    kcur = *(const float4*)ksT[g][j0 + 6 - cc];
                    float qk = q0v.x * kcur.x + q0v.y * kcur.y + q0v.z * kcur.z + q0v.w * kcur.w;
                    float qr = q0v.x * ra.x + q0v.y * ra.y + q0v.z * rb.x + q0v.w * rb.y;
                    float kr = kcur.x * rc.x + kcur.y * rc.y + kcur.z * rd.x + kcur.w * rd.y;
                    P[6 - cc] = fmaf(cqk, qk, fmaf(cqr, qr, fmaf(ckr, kr, soff)));
                }
                if (cc >= 1) {
                    float qk = q1v.x * kprev.x + q1v.y * kprev.y + q1v.z * kprev.z + q1v.w * kprev.w;
                    float qr = q1v.x * ra.x + q1v.y * ra.y + q1v.z * rb.x + q1v.w * rb.y;
                    float kr = kprev.x * rc.x + kprev.y * rc.y + kprev.z * rd.x + kprev.w * rd.y;
                    P[7 + 7 - cc] = fmaf(cqk, qk, fmaf(cqr, qr, fmaf(ckr, kr, soff)));
                }
                kprev = kcur;
            }
        }

        // ---- phase 2: exp + warp-butterfly row sums ----
        float rinv0, rinv1;
        {
            float rs0 = 0.f, rs1 = 0.f;
#pragma unroll
            for (int jj = 0; jj < 7; ++jj) {
                float p0 = __expf(P[jj]);
                float p1 = __expf(P[7 + jj]);
                P[jj] = p0; P[7 + jj] = p1;
                rs0 += p0; rs1 += p1;
            }
#pragma unroll
            for (int m = 1; m < 8; m <<= 1) {
                rs0 += __shfl_xor_sync(0xffffffffu, rs0, m);
                rs1 += __shfl_xor_sync(0xffffffffu, rs1, m);
            }
            rinv0 = 1.0f / rs0;
            rinv1 = 1.0f / rs1;
        }

        // ---- phase 3a: sv partials + warp reduce-scatter ----
        {
            float av[16];
#pragma unroll
            for (int v = 0; v < 16; ++v) av[v] = 0.f;
#pragma unroll
            for (int jj = 0; jj < 7; ++jj) {
                float4 v0 = *(const float4*)&vsT[g][j0 + jj][0];
                float4 v1 = *(const float4*)&vsT[g][j0 + jj][4];
                float p0 = P[jj], p1 = P[7 + jj];
                av[0] += p0 * v0.x; av[1] += p1 * v0.x;
                av[2] += p0 * v0.y; av[3] += p1 * v0.y;
                av[4] += p0 * v0.z; av[5] += p1 * v0.z;
                av[6] += p0 * v0.w; av[7] += p1 * v0.w;
                av[8]  += p0 * v1.x; av[9]  += p1 * v1.x;
                av[10] += p0 * v1.y; av[11] += p1 * v1.y;
                av[12] += p0 * v1.z; av[13] += p1 * v1.z;
                av[14] += p0 * v1.w; av[15] += p1 * v1.w;
            }
            float s0, s1;
            reduce_scatter16(av, tj, s0, s1);
            SB[2 * chown][i0]     = s0 * rinv0;
            SB[2 * chown][i0 + 1] = s1 * rinv1;
        }

        // ---- phase 3b: sve partials (fp16 relv rows) + reduce-scatter ----
        {
            float av[16];
#pragma unroll
            for (int v = 0; v < 16; ++v) av[v] = 0.f;
#pragma unroll
            for (int cc = 0; cc < 8; ++cc) {
                int d = dbase + cc;
                uint4 rw = *(const uint4*)relV[d];
                const __half2* hp = (const __half2*)&rw;
                float2 va = __half22float2(hp[0]);
                float2 vb = __half22float2(hp[1]);
                float2 vc = __half22float2(hp[2]);
                float2 vd = __half22float2(hp[3]);
                if (cc <= 6) {
                    float p = P[6 - cc];
                    av[0] += p * va.x; av[2]  += p * va.y; av[4]  += p * vb.x; av[6]  += p * vb.y;
                    av[8] += p * vc.x; av[10] += p * vc.y; av[12] += p * vd.x; av[14] += p * vd.y;
                }
                if (cc >= 1) {
                    float p = P[7 + 7 - cc];
                    av[1] += p * va.x; av[3]  += p * va.y; av[5]  += p * vb.x; av[7]  += p * vb.y;
                    av[9] += p * vc.x; av[11] += p * vc.y; av[13] += p * vd.x; av[15] += p * vd.y;
                }
            }
            float s0, s1;
            reduce_scatter16(av, tj, s0, s1);
            SB[2 * chown + 1][i0]     = s0 * rinv0 * 0.1f;
            SB[2 * chown + 1][i0 + 1] = s1 * rinv1 * 0.1f;
        }
        __syncthreads();

        // ---- coalesced fp16 write to g_so for this head ----
        {
            float4 v4 = *(const float4*)&SB[row_w][c4_w * 4];
            __half2 h0 = __floats2half2_rn(v4.x, v4.y);
            __half2 h1 = __floats2half2_rn(v4.z, v4.w);
            __half* ob = g_so + (size_t)b * CH_STR + g * 16 * 56 + row_w * 56 + c4_w * 4;
            uint2 st;
            st.x = *(unsigned*)&h0;
            st.y = *(unsigned*)&h1;
            *(uint2*)ob = st;
        }

        // ---- out stats (fp32, pre-quantization): 16 rows x 8 lanes ----
        if (t < 128) {
            int row = t >> 3, sub = t & 7;
            float s1 = 0.f, s2 = 0.f;
#pragma unroll
            for (int e = 0; e < 7; ++e) {
                float v = SB[row][sub * 7 + e];
                s1 += v; s2 += v * v;
            }
#pragma unroll
            for (int m = 1; m < 8; m <<= 1) {
                s1 += __shfl_xor_sync(0xffffffffu, s1, m);
                s2 += __shfl_xor_sync(0xffffffffu, s2, m);
            }
            if (sub == 0) {
                atomicAdd(&g_osum[g * 16 + row], (double)s1);
                atomicAdd(&g_osq [g * 16 + row], (double)s2);
            }
        }
        __syncthreads();   // SB consumed; safe for next head
    }
}

// ---------------- K4: out BN (folded finalize) + pair-sum + layout ----------
__global__ void __launch_bounds__(256) k_out(float* __restrict__ out,
                                             const float* __restrict__ og,
                                             const float* __restrict__ ob) {
    __shared__ float sOs[128], sOo[128];
    {
        int o = threadIdx.x;
        if (o < 128) {
            double inv = 1.0 / NQKV;
            double m = g_osum[o] * inv;
            double v = g_osq[o] * inv - m * m;
            float sc = og[o] * rsqrtf((float)v + EPSBN);
            sOs[o] = sc;
            sOo[o] = ob[o] - (float)m * sc;
        }
    }
    __syncthreads();
    int idx = blockIdx.x * 256 + threadIdx.x;
    if (idx >= 1605632) return;
    int e  = idx * 4;
    int cp = e / XPLANE;
    int r  = e % XPLANE;
    int bq = r / 56, i = r % 56;
    const __half* base = g_so + (size_t)bq * CH_STR + (2 * cp) * 56 + i;
    uint2 a = *(const uint2*)base;
    uint2 bb = *(const uint2*)(base + 56);
    __half2 ha0, ha1, hb0, hb1;
    *(unsigned*)&ha0 = a.x;  *(unsigned*)&ha1 = a.y;
    *(unsigned*)&hb0 = bb.x; *(unsigned*)&hb1 = bb.y;
    float2 s0a = __half22float2(ha0), s0b = __half22float2(ha1);
    float2 s1a = __half22float2(hb0), s1b = __half22float2(hb1);
    float sc0 = sOs[2 * cp], of0 = sOo[2 * cp];
    float sc1 = sOs[2 * cp + 1], of1 = sOo[2 * cp + 1];
    float4 o4;
    o4.x = s0a.x * sc0 + of0 + s1a.x * sc1 + of1;
    o4.y = s0a.y * sc0 + of0 + s1a.y * sc1 + of1;
    o4.z = s0b.x * sc0 + of0 + s1b.x * sc1 + of1;
    o4.w = s0b.y * sc0 + of0 + s1b.y * sc1 + of1;
    *(float4*)&out[e] = o4;
}

// ---------------- launch -----------------------------------------------------
extern "C" void kernel_launch(void* const* d_in, const int* in_sizes, int n_in,
                              void* d_out, int out_size) {
    const float* x        = (const float*)d_in[0];
    const float* w_qkv    = (const float*)d_in[1];
    const float* relative = (const float*)d_in[2];
    const float* qg       = (const float*)d_in[3];
    const float* qb       = (const float*)d_in[4];
    const float* sg       = (const float*)d_in[5];
    const float* sb       = (const float*)d_in[6];
    const float* og       = (const float*)d_in[7];
    const float* ob       = (const float*)d_in[8];
    float* out            = (float*)d_out;

    k_init <<<1, 256>>>(relative);
    k_qkv  <<<BTOT, 128>>>(x, w_qkv);
    k_mom  <<<BTOT, 256>>>(qg, qb);
    k_attn <<<BTOT, 224>>>(relative, qg, qb, sg, sb);
    k_out  <<<6272, 256>>>(out, og, ob);
}